// round 7
// baseline (speedup 1.0000x reference)
#include <cuda_runtime.h>
#include <cstdint>

typedef unsigned long long ull;

#define MAXN (1 << 21)

// g_nodes[i] packs {p : lo 32, sum : hi 32} in one 8B word. Final state:
// p == N, hi = full path sum. Nodes < N/8 are finalized by the resolve
// kernels; the rest are finalized on demand by the gather kernel.
__device__ ull g_nodes[MAXN];

__device__ __forceinline__ ull pack_node(unsigned p, float t) {
    return ((ull)__float_as_uint(t) << 32) | (ull)p;
}
__device__ __forceinline__ ull ld_cg(const ull* a) {
    ull v;
    asm volatile("ld.relaxed.gpu.b64 %0, [%1];" : "=l"(v) : "l"(a) : "memory");
    return v;
}
__device__ __forceinline__ void st_cg(ull* a, ull v) {
    asm volatile("st.relaxed.gpu.b64 [%0], %1;" :: "l"(a), "l"(v) : "memory");
}

__device__ __forceinline__ float node_score(const float* f, const float* w, float b)
{
    float z = b;
    z += w[0] * f[0] + w[1] * f[1] + w[2] * f[2] + w[3] * f[3] + w[4] * f[4];
    #pragma unroll
    for (int j = 6; j < 15; j++)
        z += w[j - 1] * __logf(fabsf(f[j]) + 1e-10f);
    z += w[14] * (sqrtf(f[7]) / (sqrtf(f[6]) + 1e-10f));
    float sn, cs;
    __sincosf(f[5], &sn, &cs);
    z += w[15] * cs + w[16] * sn;
    return 1.0f / (1.0f + __expf(-z));
}

// ---------------------------------------------------------------------------
// Phase 1: 512 nodes per 256-thread block. term = diff * sigmoid(linear(
// rescale(attr))); publish (parent, term) per node.
// ---------------------------------------------------------------------------
__global__ __launch_bounds__(256)
void phase1_kernel(const float* __restrict__ diff,
                   const float* __restrict__ attr,
                   const float* __restrict__ weight,
                   const float* __restrict__ bias,
                   const int*   __restrict__ parent,
                   int N)
{
    __shared__ float s_attr[512 * 15];
    const int base = blockIdx.x * 512;
    const int tid  = threadIdx.x;
    const int i0   = base + tid;
    const int i1   = base + tid + 256;

    float d0 = 0.0f, d1 = 0.0f;
    int   q0 = 0,    q1 = 0;
    if (i0 < N) { d0 = __ldcs(diff + i0); q0 = __ldcs(parent + i0); }
    if (i1 < N) { d1 = __ldcs(diff + i1); q1 = __ldcs(parent + i1); }

    if (base + 512 <= N) {
        const float4* src = (const float4*)(attr + (size_t)base * 15);
        float4* dst = (float4*)s_attr;
        #pragma unroll
        for (int k = 0; k < 7; k++)
            dst[tid + k * 256] = __ldcs(src + tid + k * 256);
        if (tid < 128) dst[tid + 1792] = __ldcs(src + tid + 1792);
    } else {
        const int rem = (N - base) * 15;
        for (int k = tid; k < rem; k += 256)
            s_attr[k] = __ldcs(attr + (size_t)base * 15 + k);
    }
    __syncthreads();

    float w[17];
    #pragma unroll
    for (int k = 0; k < 17; k++) w[k] = __ldg(weight + k);
    const float b = __ldg(bias);

    if (i0 < N) {
        const float t = d0 * node_score(s_attr + tid * 15, w, b);
        g_nodes[i0] = pack_node((q0 < 0) ? (unsigned)N : (unsigned)q0, t);
    }
    if (i1 < N) {
        const float t = d1 * node_score(s_attr + (tid + 256) * 15, w, b);
        g_nodes[i1] = pack_node((q1 < 0) ? (unsigned)N : (unsigned)q1, t);
    }
}

// ---------------------------------------------------------------------------
// Resolve slab [start, end), 1 thread/node, read-only chase, single final
// publish. Invariant: nodes < start are final. parent[i] < i guarantees
// termination; races publish identical-within-rounding states.
// ---------------------------------------------------------------------------
__global__ __launch_bounds__(256)
void resolve_slab_kernel(int start, int end, int N)
{
    const int i = start + blockIdx.x * blockDim.x + threadIdx.x;
    if (i >= end) return;
    const unsigned Nu = (unsigned)N;

    ull cur = __ldg(&g_nodes[i]);
    unsigned p = (unsigned)cur;
    float    t = __uint_as_float((unsigned)(cur >> 32));

    while (p != Nu) {
        const ull m = __ldg(&g_nodes[p]);
        t += __uint_as_float((unsigned)(m >> 32));
        p = (unsigned)m;
    }
    st_cg(&g_nodes[i], pack_node(Nu, t));
}

// ---------------------------------------------------------------------------
// Fused gather + on-demand resolve. Nodes < resolved_bound are final; for
// others, the first toucher chases (each hop: one 8B L2 load; ancestors
// strictly decrease, bottoming out in the resolved region) and publishes the
// final state so later touchers (avg 8 pixels/node) read it directly. Chase
// latency hides inside this wavefront-throughput-bound kernel instead of
// costing separate wall-clock in a latency-bound resolve kernel.
// ---------------------------------------------------------------------------
__global__ __launch_bounds__(256)
void gather_kernel(const int* __restrict__ pn, float* __restrict__ out,
                   int M, int N)
{
    const unsigned Nu = (unsigned)N;
    const int j  = blockIdx.x * blockDim.x + threadIdx.x;
    const int i8 = j * 8;

    if (i8 + 7 < M) {
        const int4 pa = __ldcs((const int4*)pn + 2 * j);
        const int4 pb = __ldcs((const int4*)pn + 2 * j + 1);
        int idx[8] = {pa.x, pa.y, pa.z, pa.w, pb.x, pb.y, pb.z, pb.w};

        // Front-batch the 8 independent random loads (MLP).
        ull m[8];
        #pragma unroll
        for (int k = 0; k < 8; k++) m[k] = ld_cg(&g_nodes[idx[k]]);

        float o[8];
        #pragma unroll
        for (int k = 0; k < 8; k++) {
            unsigned p = (unsigned)m[k];
            float    s = __uint_as_float((unsigned)(m[k] >> 32));
            if (p != Nu) {
                do {
                    const ull mm = ld_cg(&g_nodes[p]);
                    s += __uint_as_float((unsigned)(mm >> 32));
                    p = (unsigned)mm;
                } while (p != Nu);
                st_cg(&g_nodes[idx[k]], pack_node(Nu, s));  // publish final
            }
            o[k] = s;
        }

        float4 oa = {o[0], o[1], o[2], o[3]};
        float4 ob = {o[4], o[5], o[6], o[7]};
        __stcs((float4*)out + 2 * j, oa);
        __stcs((float4*)out + 2 * j + 1, ob);
    } else {
        for (int k = i8; k < M; k++) {
            const int idx = __ldcs(pn + k);
            ull cur = ld_cg(&g_nodes[idx]);
            unsigned p = (unsigned)cur;
            float    s = __uint_as_float((unsigned)(cur >> 32));
            while (p != Nu) {
                const ull mm = ld_cg(&g_nodes[p]);
                s += __uint_as_float((unsigned)(mm >> 32));
                p = (unsigned)mm;
            }
            out[k] = s;
        }
    }
}

extern "C" void kernel_launch(void* const* d_in, const int* in_sizes, int n_in,
                              void* d_out, int out_size)
{
    const float* diff   = (const float*)d_in[0];
    const float* attr   = (const float*)d_in[1];
    const float* weight = (const float*)d_in[2];
    const float* bias   = (const float*)d_in[3];
    const int*   parent = (const int*)d_in[4];
    const int*   pn     = (const int*)d_in[5];
    float*       out    = (float*)d_out;

    const int N = in_sizes[0];
    const int M = out_size;

    phase1_kernel<<<(N + 511) / 512, 256>>>(diff, attr, weight, bias, parent, N);

    // Pre-resolve only [0, N/8): slab [0, N/64) then [N/64, N/8).
    const int b1 = (N >> 6) > 0 ? (N >> 6) : N;
    const int b2 = (N >> 3) > b1 ? (N >> 3) : N;
    if (b1 > 0)
        resolve_slab_kernel<<<(b1 + 255) / 256, 256>>>(0, b1, N);
    if (b2 > b1)
        resolve_slab_kernel<<<(b2 - b1 + 255) / 256, 256>>>(b1, b2, N);

    // Fused gather + on-demand resolve of [N/8, N).
    const int gthreads = (M + 7) / 8;
    gather_kernel<<<(gthreads + 255) / 256, 256>>>(pn, out, M, N);
}

// round 8
// speedup vs baseline: 1.2944x; 1.2944x over previous
#include <cuda_runtime.h>
#include <cstdint>

typedef unsigned long long ull;

#define MAXN (1 << 21)

// g_nodes[i] packs {p : lo 32, sum : hi 32} in one 8B word. Final state:
// p == N, hi = full path sum. Gather reads the hi word.
__device__ ull g_nodes[MAXN];

__device__ __forceinline__ ull pack_node(unsigned p, float t) {
    return ((ull)__float_as_uint(t) << 32) | (ull)p;
}
__device__ __forceinline__ void st_cg(ull* a, ull v) {
    asm volatile("st.relaxed.gpu.b64 [%0], %1;" :: "l"(a), "l"(v) : "memory");
}

__device__ __forceinline__ float node_score(const float* f, const float* w, float b)
{
    float z = b;
    z += w[0] * f[0] + w[1] * f[1] + w[2] * f[2] + w[3] * f[3] + w[4] * f[4];
    #pragma unroll
    for (int j = 6; j < 15; j++)
        z += w[j - 1] * __logf(fabsf(f[j]) + 1e-10f);
    z += w[14] * (sqrtf(f[7]) / (sqrtf(f[6]) + 1e-10f));
    float sn, cs;
    __sincosf(f[5], &sn, &cs);
    z += w[15] * cs + w[16] * sn;
    return 1.0f / (1.0f + __expf(-z));
}

// ---------------------------------------------------------------------------
// Phase 1: 768 nodes per 256-thread block (3 nodes/thread, 45KB SMEM stage).
// ~11 front-batched float4 loads/thread for deep DRAM MLP. Computes
// term = diff * sigmoid(linear(rescale(attr))); publishes (parent, term).
// ---------------------------------------------------------------------------
__global__ __launch_bounds__(256)
void phase1_kernel(const float* __restrict__ diff,
                   const float* __restrict__ attr,
                   const float* __restrict__ weight,
                   const float* __restrict__ bias,
                   const int*   __restrict__ parent,
                   int N)
{
    __shared__ float s_attr[768 * 15];       // 46080 B
    const int base = blockIdx.x * 768;
    const int tid  = threadIdx.x;

    // Prefetch per-node scalars (overlap with the float4 stream).
    float d[3] = {0.f, 0.f, 0.f};
    int   q[3] = {0, 0, 0};
    #pragma unroll
    for (int k = 0; k < 3; k++) {
        const int i = base + tid + k * 256;
        if (i < N) { d[k] = __ldcs(diff + i); q[k] = __ldcs(parent + i); }
    }

    if (base + 768 <= N) {
        const float4* src = (const float4*)(attr + (size_t)base * 15);
        float4* dst = (float4*)s_attr;
        // 768*15/4 = 2880 float4s per block
        #pragma unroll
        for (int k = 0; k < 11; k++)
            dst[tid + k * 256] = __ldcs(src + tid + k * 256);
        if (tid < 64) dst[tid + 2816] = __ldcs(src + tid + 2816);
    } else {
        const int rem = (N - base) * 15;
        for (int k = tid; k < rem; k += 256)
            s_attr[k] = __ldcs(attr + (size_t)base * 15 + k);
    }
    __syncthreads();

    float w[17];
    #pragma unroll
    for (int k = 0; k < 17; k++) w[k] = __ldg(weight + k);
    const float b = __ldg(bias);

    #pragma unroll
    for (int k = 0; k < 3; k++) {
        const int i = base + tid + k * 256;
        if (i < N) {
            const float t = d[k] * node_score(s_attr + (tid + k * 256) * 15, w, b);
            g_nodes[i] = pack_node((q[k] < 0) ? (unsigned)N : (unsigned)q[k], t);
        }
    }
}

// ---------------------------------------------------------------------------
// Resolve slab [start, end), 1 thread/node, read-only chase, single final
// publish. Invariant: nodes < start are final (p == N). parent[i] < i =>
// termination. Stale L1 reads of in-slab nodes return the original
// (parent, term) state — still valid; races publish identical sums.
// ---------------------------------------------------------------------------
__global__ __launch_bounds__(256)
void resolve_slab_kernel(int start, int end, int N)
{
    const int i = start + blockIdx.x * blockDim.x + threadIdx.x;
    if (i >= end) return;
    const unsigned Nu = (unsigned)N;

    ull cur = __ldg(&g_nodes[i]);
    unsigned p = (unsigned)cur;
    float    t = __uint_as_float((unsigned)(cur >> 32));

    while (p != Nu) {
        const ull m = __ldg(&g_nodes[p]);
        t += __uint_as_float((unsigned)(m >> 32));
        p = (unsigned)m;
    }
    st_cg(&g_nodes[i], pack_node(Nu, t));
}

// ---------------------------------------------------------------------------
// Gather: out[j] = hi32(g_nodes[pn[j]]). Pure wavefront-throughput kernel:
// 8 front-batched independent random loads/thread; streaming hints keep the
// 128MB pixel traffic from evicting the 16MB g_nodes from L2.
// ---------------------------------------------------------------------------
__global__ __launch_bounds__(256)
void gather_kernel(const int* __restrict__ pn, float* __restrict__ out, int M)
{
    const int j  = blockIdx.x * blockDim.x + threadIdx.x;
    const int i8 = j * 8;
    if (i8 + 7 < M) {
        const int4 pa = __ldcs((const int4*)pn + 2 * j);
        const int4 pb = __ldcs((const int4*)pn + 2 * j + 1);
        float4 oa, ob;
        oa.x = __uint_as_float((unsigned)(__ldg(&g_nodes[pa.x]) >> 32));
        oa.y = __uint_as_float((unsigned)(__ldg(&g_nodes[pa.y]) >> 32));
        oa.z = __uint_as_float((unsigned)(__ldg(&g_nodes[pa.z]) >> 32));
        oa.w = __uint_as_float((unsigned)(__ldg(&g_nodes[pa.w]) >> 32));
        ob.x = __uint_as_float((unsigned)(__ldg(&g_nodes[pb.x]) >> 32));
        ob.y = __uint_as_float((unsigned)(__ldg(&g_nodes[pb.y]) >> 32));
        ob.z = __uint_as_float((unsigned)(__ldg(&g_nodes[pb.z]) >> 32));
        ob.w = __uint_as_float((unsigned)(__ldg(&g_nodes[pb.w]) >> 32));
        __stcs((float4*)out + 2 * j, oa);
        __stcs((float4*)out + 2 * j + 1, ob);
    } else {
        for (int k = i8; k < M; k++)
            out[k] = __uint_as_float((unsigned)(__ldg(&g_nodes[__ldcs(pn + k)]) >> 32));
    }
}

extern "C" void kernel_launch(void* const* d_in, const int* in_sizes, int n_in,
                              void* d_out, int out_size)
{
    const float* diff   = (const float*)d_in[0];
    const float* attr   = (const float*)d_in[1];
    const float* weight = (const float*)d_in[2];
    const float* bias   = (const float*)d_in[3];
    const int*   parent = (const int*)d_in[4];
    const int*   pn     = (const int*)d_in[5];
    float*       out    = (float*)d_out;

    const int N = in_sizes[0];
    const int M = out_size;

    phase1_kernel<<<(N + 767) / 768, 256>>>(diff, attr, weight, bias, parent, N);

    // 3 slabs: [0, N/64), [N/64, N/8), [N/8, N); 1 thread per node.
    const int b1 = (N >> 6) > 0 ? (N >> 6) : N;
    const int b2 = (N >> 3) > b1 ? (N >> 3) : N;
    if (b1 > 0)
        resolve_slab_kernel<<<(b1 + 255) / 256, 256>>>(0, b1, N);
    if (b2 > b1)
        resolve_slab_kernel<<<(b2 - b1 + 255) / 256, 256>>>(b1, b2, N);
    if (N > b2)
        resolve_slab_kernel<<<(N - b2 + 255) / 256, 256>>>(b2, N, N);

    const int gthreads = (M + 7) / 8;
    gather_kernel<<<(gthreads + 255) / 256, 256>>>(pn, out, M);
}

// round 9
// speedup vs baseline: 1.3603x; 1.0509x over previous
#include <cuda_runtime.h>
#include <cstdint>

typedef unsigned long long ull;

#define MAXN (1 << 21)

// g_nodes[i] packs {p : lo 32, sum : hi 32} in one 8B word. Final state:
// p == N, hi = full path sum. Gather reads the hi word.
__device__ ull g_nodes[MAXN];

__device__ __forceinline__ ull pack_node(unsigned p, float t) {
    return ((ull)__float_as_uint(t) << 32) | (ull)p;
}
__device__ __forceinline__ void st_cg(ull* a, ull v) {
    asm volatile("st.relaxed.gpu.b64 [%0], %1;" :: "l"(a), "l"(v) : "memory");
}

__device__ __forceinline__ float node_score(const float* f, const float* w, float b)
{
    float z = b;
    z += w[0] * f[0] + w[1] * f[1] + w[2] * f[2] + w[3] * f[3] + w[4] * f[4];
    #pragma unroll
    for (int j = 6; j < 15; j++)
        z += w[j - 1] * __logf(fabsf(f[j]) + 1e-10f);
    z += w[14] * (sqrtf(f[7]) / (sqrtf(f[6]) + 1e-10f));
    float sn, cs;
    __sincosf(f[5], &sn, &cs);
    z += w[15] * cs + w[16] * sn;
    return 1.0f / (1.0f + __expf(-z));
}

// ---------------------------------------------------------------------------
// Phase 1: 768 nodes per 256-thread block (3 nodes/thread, 45KB SMEM stage).
// term = diff * sigmoid(linear(rescale(attr))); publish (parent, term).
// ---------------------------------------------------------------------------
__global__ __launch_bounds__(256)
void phase1_kernel(const float* __restrict__ diff,
                   const float* __restrict__ attr,
                   const float* __restrict__ weight,
                   const float* __restrict__ bias,
                   const int*   __restrict__ parent,
                   int N)
{
    __shared__ float s_attr[768 * 15];
    const int base = blockIdx.x * 768;
    const int tid  = threadIdx.x;

    float d[3] = {0.f, 0.f, 0.f};
    int   q[3] = {0, 0, 0};
    #pragma unroll
    for (int k = 0; k < 3; k++) {
        const int i = base + tid + k * 256;
        if (i < N) { d[k] = __ldcs(diff + i); q[k] = __ldcs(parent + i); }
    }

    if (base + 768 <= N) {
        const float4* src = (const float4*)(attr + (size_t)base * 15);
        float4* dst = (float4*)s_attr;
        #pragma unroll
        for (int k = 0; k < 11; k++)
            dst[tid + k * 256] = __ldcs(src + tid + k * 256);
        if (tid < 64) dst[tid + 2816] = __ldcs(src + tid + 2816);
    } else {
        const int rem = (N - base) * 15;
        for (int k = tid; k < rem; k += 256)
            s_attr[k] = __ldcs(attr + (size_t)base * 15 + k);
    }
    __syncthreads();

    float w[17];
    #pragma unroll
    for (int k = 0; k < 17; k++) w[k] = __ldg(weight + k);
    const float b = __ldg(bias);

    #pragma unroll
    for (int k = 0; k < 3; k++) {
        const int i = base + tid + k * 256;
        if (i < N) {
            const float t = d[k] * node_score(s_attr + (tid + k * 256) * 15, w, b);
            g_nodes[i] = pack_node((q[k] < 0) ? (unsigned)N : (unsigned)q[k], t);
        }
    }
}

// ---------------------------------------------------------------------------
// Resolve slab [start, end), 1 thread/node, read-only chase, single final
// publish. Invariant: nodes < start are final (p == N). parent[i] < i =>
// termination. Slab ratios chosen by the wavefront model:
// E[in-slab hops](ratio r) = (r ln r - (r-1))/(r-1); +1 terminal hop.
// ---------------------------------------------------------------------------
__global__ __launch_bounds__(256)
void resolve_slab_kernel(int start, int end, int N)
{
    const int i = start + blockIdx.x * blockDim.x + threadIdx.x;
    if (i >= end) return;
    const unsigned Nu = (unsigned)N;

    ull cur = __ldg(&g_nodes[i]);
    unsigned p = (unsigned)cur;
    float    t = __uint_as_float((unsigned)(cur >> 32));

    while (p != Nu) {
        const ull m = __ldg(&g_nodes[p]);
        t += __uint_as_float((unsigned)(m >> 32));
        p = (unsigned)m;
    }
    st_cg(&g_nodes[i], pack_node(Nu, t));
}

// ---------------------------------------------------------------------------
// Gather: out[j] = hi32(g_nodes[pn[j]]). 4 pixels/thread (MLP_p1 ~ 5) to
// reduce cross-CTA l1tex queue-contention spread while staying at the
// wavefront-throughput floor. Streaming hints keep the 128MB pixel traffic
// from evicting the 16MB g_nodes from L2.
// ---------------------------------------------------------------------------
__global__ __launch_bounds__(256)
void gather_kernel(const int* __restrict__ pn, float* __restrict__ out, int M)
{
    const int j  = blockIdx.x * blockDim.x + threadIdx.x;
    const int i4 = j * 4;
    if (i4 + 3 < M) {
        const int4 p = __ldcs((const int4*)pn + j);
        float4 o;
        o.x = __uint_as_float((unsigned)(__ldg(&g_nodes[p.x]) >> 32));
        o.y = __uint_as_float((unsigned)(__ldg(&g_nodes[p.y]) >> 32));
        o.z = __uint_as_float((unsigned)(__ldg(&g_nodes[p.z]) >> 32));
        o.w = __uint_as_float((unsigned)(__ldg(&g_nodes[p.w]) >> 32));
        __stcs((float4*)out + j, o);
    } else {
        for (int k = i4; k < M; k++)
            out[k] = __uint_as_float((unsigned)(__ldg(&g_nodes[__ldcs(pn + k)]) >> 32));
    }
}

extern "C" void kernel_launch(void* const* d_in, const int* in_sizes, int n_in,
                              void* d_out, int out_size)
{
    const float* diff   = (const float*)d_in[0];
    const float* attr   = (const float*)d_in[1];
    const float* weight = (const float*)d_in[2];
    const float* bias   = (const float*)d_in[3];
    const int*   parent = (const int*)d_in[4];
    const int*   pn     = (const int*)d_in[5];
    float*       out    = (float*)d_out;

    const int N = in_sizes[0];
    const int M = out_size;

    phase1_kernel<<<(N + 767) / 768, 256>>>(diff, attr, weight, bias, parent, N);

    // Slabs: [0,N/64), [N/64,N/8), [N/8,N/2), [N/2,N).
    const int b1 = N >> 6;
    const int b2 = N >> 3;
    const int b3 = N >> 1;
    if (b1 > 0)
        resolve_slab_kernel<<<(b1 + 255) / 256, 256>>>(0, b1, N);
    if (b2 > b1)
        resolve_slab_kernel<<<(b2 - b1 + 255) / 256, 256>>>(b1, b2, N);
    if (b3 > b2)
        resolve_slab_kernel<<<(b3 - b2 + 255) / 256, 256>>>(b2, b3, N);
    if (N > b3)
        resolve_slab_kernel<<<(N - b3 + 255) / 256, 256>>>(b3, N, N);

    const int gthreads = (M + 3) / 4;
    gather_kernel<<<(gthreads + 255) / 256, 256>>>(pn, out, M);
}